// round 17
// baseline (speedup 1.0000x reference)
#include <cuda_runtime.h>
#include <cuda_fp16.h>
#include <math.h>

#define N_NODES 100000
#define N_EDGES 1000000
#define EHALF   (N_EDGES / 2)
#define F 32
#define DFEAT 160            // 5 segments x 32
#define BM 128               // GEMM M tile
#define NHF4 (N_NODES * F / 8)   // float4 count per fp16 [N,F] array = 400000

// ---------------- scratch (device globals; no allocation) ----------------
__device__ __align__(16) float  g_deg[2 * N_NODES];        // [deg_out | deg_in]
__device__ __align__(16) int4   g_eP[N_EDGES];             // {src, dst, no_h2, ni_h2}
__device__ __align__(16) __half g_X16 [N_NODES * F];       // fp16 mirror of X
__device__ __align__(16) __half g_T1o16[N_NODES * F];      // fp16 accumulators (hop 1)
__device__ __align__(16) __half g_T1i16[N_NODES * F];
__device__ __align__(16) __half g_P2o16[N_NODES * F];      // fp16 accumulators (hop 2)
__device__ __align__(16) __half g_P2i16[N_NODES * F];
__device__ __align__(16) float  g_W[DFEAT * 64];           // [f][64]: cols 0-31 Wz_eff, 32-63 Wh_eff

// ---------------- helpers ----------------
// 16-byte fp16 vector reduction: adds 8 halves in one L2 atomic op (sm_90+)
__device__ __forceinline__ void red4h(__half* p, __half2 a, __half2 b, __half2 c, __half2 d) {
    unsigned ua = *(unsigned*)&a, ub = *(unsigned*)&b, uc = *(unsigned*)&c, ud = *(unsigned*)&d;
    asm volatile("red.global.add.noftz.v4.f16x2 [%0], {%1,%2,%3,%4};"
                 :: "l"(p), "r"(ua), "r"(ub), "r"(uc), "r"(ud) : "memory");
}
// scale a gathered 16B fp16 row (float4 = 4x half2) by a broadcast half2 and reduce
__device__ __forceinline__ void scale_red(__half* p, float4 r, unsigned nbits) {
    __half2 nh = *(__half2*)&nbits;
    __half2 a = __hmul2(*(__half2*)&r.x, nh);
    __half2 b = __hmul2(*(__half2*)&r.y, nh);
    __half2 c = __hmul2(*(__half2*)&r.z, nh);
    __half2 d = __hmul2(*(__half2*)&r.w, nh);
    red4h(p, a, b, c, d);
}
__device__ __forceinline__ float tf32r(float x) {
    unsigned u;
    asm("cvt.rna.tf32.f32 %0, %1;" : "=r"(u) : "f"(x));
    return __uint_as_float(u);
}
__device__ __forceinline__ void mma_tf32(float c[4], unsigned a0, unsigned a1, unsigned a2,
                                         unsigned a3, unsigned b0, unsigned b1) {
    asm("mma.sync.aligned.m16n8k8.row.col.f32.tf32.tf32.f32 "
        "{%0,%1,%2,%3}, {%4,%5,%6,%7}, {%8,%9}, {%0,%1,%2,%3};"
        : "+f"(c[0]), "+f"(c[1]), "+f"(c[2]), "+f"(c[3])
        : "r"(a0), "r"(a1), "r"(a2), "r"(a3), "r"(b0), "r"(b1));
}
__device__ __forceinline__ float4 unpack4h(float2 r) { // 4 halves (as float2 bits) -> 4 floats
    __half2 h01 = *(__half2*)&r.x;
    __half2 h23 = *(__half2*)&r.y;
    float2 f01 = __half22float2(h01);
    float2 f23 = __half22float2(h23);
    return make_float4(f01.x, f01.y, f23.x, f23.y);
}
__device__ __forceinline__ float2 pack4h(float4 v) {   // 4 floats -> 4 halves as float2 bits
    __half2 p01 = __floats2half2_rn(v.x, v.y);
    __half2 p23 = __floats2half2_rn(v.z, v.w);
    float2 r;
    r.x = __uint_as_float(*(unsigned*)&p01);
    r.y = __uint_as_float(*(unsigned*)&p23);
    return r;
}

// ---------------- kernels ----------------
// branch A: zero fp16 accumulators + build X16 (independent of the deg/pack chain)
__global__ void zero_x16_kernel(const float* __restrict__ X) {
    int i = blockIdx.x * blockDim.x + threadIdx.x;
    if (i >= NHF4) return;
    float4 z = make_float4(0.f, 0.f, 0.f, 0.f);
    ((float4*)g_T1o16)[i] = z;
    ((float4*)g_T1i16)[i] = z;
    ((float4*)g_P2o16)[i] = z;
    ((float4*)g_P2i16)[i] = z;
    float2 lo = pack4h(((const float4*)X)[2 * i]);
    float2 hi = pack4h(((const float4*)X)[2 * i + 1]);
    ((float4*)g_X16)[i] = make_float4(lo.x, lo.y, hi.x, hi.y);
}

// main chain: weighted-degree atomics (g_deg zeroed beforehand by cudaMemsetAsync)
__global__ void deg_kernel(const int* __restrict__ src, const int* __restrict__ dst,
                           const float* __restrict__ ew) {
    int e = blockIdx.x * blockDim.x + threadIdx.x;
    if (e >= N_EDGES) return;
    float w = ew[e];
    atomicAdd(&g_deg[src[e]], w);
    atomicAdd(&g_deg[N_NODES + dst[e]], w);
}

// FUSED: pack {src, dst, no_h2, ni_h2} per edge (norms as broadcast half2) + W_eff build.
__global__ void pack_wprep_kernel(const int* __restrict__ src, const int* __restrict__ dst,
                                  const float* __restrict__ ew,
                                  const float* __restrict__ Wz, const float* __restrict__ Wh) {
    int e = blockIdx.x * blockDim.x + threadIdx.x;
    if (e < N_EDGES) {
        int s = src[e], d = dst[e];
        float w = ew[e];
        float no = w / g_deg[s];
        float ni = w / g_deg[N_NODES + d];
        __half2 noh = __float2half2_rn(no);
        __half2 nih = __float2half2_rn(ni);
        g_eP[e] = make_int4(s, d, *(int*)&noh, *(int*)&nih);
    }
    if (e < 2 * DFEAT * F) {
        int idx = e;
        int gate = idx / (DFEAT * F);
        int rem  = idx % (DFEAT * F);
        int f = rem / F, j = rem % F;
        int seg = f >> 5, r = f & 31;
        const float* W = gate ? Wh : Wz;
        float v;
        if (seg == 0)      v = W[(0 * 64 + r) * 32 + j] + W[(3 * 64 + r) * 32 + j]
                             - W[(2 * 64 + r) * 32 + j] - W[(5 * 64 + r) * 32 + j];
        else if (seg == 1) v = W[(1 * 64 + r) * 32 + j];
        else if (seg == 2) v = W[(4 * 64 + r) * 32 + j];
        else if (seg == 3) v = 2.f * W[(2 * 64 + r) * 32 + j];
        else               v = 2.f * W[(5 * 64 + r) * 32 + j];
        g_W[f * 64 + gate * 32 + j] = v;
    }
}

// hop 1, ILP=2, pure fp16 path: gather 16B of X16, HMUL2 by norm, vector-red.
__global__ void prop1_kernel() {
    long idx = (long)blockIdx.x * blockDim.x + threadIdx.x;
    int e0 = (int)(idx >> 3);
    if (e0 >= EHALF) return;
    int e1 = e0 + EHALF;
    int h = (int)(idx & 7);
    int dir = h >> 2, l = h & 3;
    int4 epA = g_eP[e0];
    int4 epB = g_eP[e1];
    if (dir == 0) {
        float4 rA = ((const float4*)g_X16)[epA.x * 4 + l];
        float4 rB = ((const float4*)g_X16)[epB.x * 4 + l];
        scale_red(&g_T1o16[epA.y * F + 8 * l], rA, (unsigned)epA.z);
        scale_red(&g_T1o16[epB.y * F + 8 * l], rB, (unsigned)epB.z);
    } else {
        float4 rA = ((const float4*)g_X16)[epA.y * 4 + l];
        float4 rB = ((const float4*)g_X16)[epB.y * 4 + l];
        scale_red(&g_T1i16[epA.x * F + 8 * l], rA, (unsigned)epA.w);
        scale_red(&g_T1i16[epB.x * F + 8 * l], rB, (unsigned)epB.w);
    }
}

// hop 2, ILP=2, pure fp16 path.
__global__ void prop2_kernel() {
    long idx = (long)blockIdx.x * blockDim.x + threadIdx.x;
    int e0 = (int)(idx >> 3);
    if (e0 >= EHALF) return;
    int e1 = e0 + EHALF;
    int h = (int)(idx & 7);
    int dir = h >> 2, l = h & 3;
    int4 epA = g_eP[e0];
    int4 epB = g_eP[e1];
    if (dir == 0) {
        float4 rA = ((const float4*)g_T1o16)[epA.x * 4 + l];
        float4 rB = ((const float4*)g_T1o16)[epB.x * 4 + l];
        scale_red(&g_P2o16[epA.y * F + 8 * l], rA, (unsigned)epA.z);
        scale_red(&g_P2o16[epB.y * F + 8 * l], rB, (unsigned)epB.z);
    } else {
        float4 rA = ((const float4*)g_T1i16)[epA.y * 4 + l];
        float4 rB = ((const float4*)g_T1i16)[epB.y * 4 + l];
        scale_red(&g_P2i16[epA.x * F + 8 * l], rA, (unsigned)epA.w);
        scale_red(&g_P2i16[epB.x * F + 8 * l], rB, (unsigned)epB.w);
    }
}

// ---------------- tensor-core GEMM + fused GRU epilogue ----------------
// [BM x 160] @ [160 x 64] via mma.sync.m16n8k8.tf32. ALL segments read fp16
// (seg 0 = X16 mirror; fp16 -> tf32 exact), uniform A-loader.
__global__ __launch_bounds__(128) void gemm_kernel(
    const float* __restrict__ bz, const float* __restrict__ bh,
    const float* __restrict__ wl, const float* __restrict__ bl,
    float* __restrict__ out)
{
    __shared__ __align__(16) float As[BM][36];   // [m][k]
    __shared__ __align__(16) float Bs[32][72];   // [k][n]

    int tid  = threadIdx.x;
    int w    = tid >> 5;
    int lane = tid & 31;
    int g    = lane >> 2;      // 0..7
    int tg   = lane & 3;       // 0..3
    int blockm = blockIdx.x * BM;

    float c[2][8][4];
#pragma unroll
    for (int mf = 0; mf < 2; mf++)
#pragma unroll
        for (int n = 0; n < 8; n++)
#pragma unroll
            for (int k = 0; k < 4; k++) c[mf][n][k] = 0.f;

    const __half* seg16[5] = { g_X16, g_T1o16, g_T1i16, g_P2o16, g_P2i16 };

    for (int ks = 0; ks < 5; ks++) {
        const __half* A = seg16[ks];
        // A tile: 128 nodes x 32 feats, fp16 -> f32 (tf32-exact)
#pragma unroll
        for (int i = 0; i < 8; i++) {
            int idx = i * 128 + tid;          // 0..1023
            int m  = idx >> 3;
            int f4 = idx & 7;
            int node = blockm + m;
            float2 r = (node < N_NODES) ? ((const float2*)A)[node * 8 + f4]
                                        : make_float2(0.f, 0.f);
            *(float4*)&As[m][f4 * 4] = unpack4h(r);
        }
        // B tile: 32 x 64, tf32-rounded
#pragma unroll
        for (int i = 0; i < 4; i++) {
            int fidx = i * 128 + tid;         // float4 idx, 0..511
            float4 v = ((const float4*)g_W)[ks * 512 + fidx];
            int r  = fidx >> 4;
            int c4 = (fidx & 15) * 4;
            float4 t = make_float4(tf32r(v.x), tf32r(v.y), tf32r(v.z), tf32r(v.w));
            *(float4*)&Bs[r][c4] = t;
        }
        __syncthreads();

#pragma unroll
        for (int kst = 0; kst < 4; kst++) {
            int kb = kst * 8;
            unsigned a[2][4];
#pragma unroll
            for (int mf = 0; mf < 2; mf++) {
                int mb = w * 32 + mf * 16;
                a[mf][0] = __float_as_uint(As[mb + g    ][kb + tg    ]);
                a[mf][1] = __float_as_uint(As[mb + g + 8][kb + tg    ]);
                a[mf][2] = __float_as_uint(As[mb + g    ][kb + tg + 4]);
                a[mf][3] = __float_as_uint(As[mb + g + 8][kb + tg + 4]);
            }
#pragma unroll
            for (int n = 0; n < 8; n++) {
                unsigned b0 = __float_as_uint(Bs[kb + tg    ][n * 8 + g]);
                unsigned b1 = __float_as_uint(Bs[kb + tg + 4][n * 8 + g]);
                mma_tf32(c[0][n], a[0][0], a[0][1], a[0][2], a[0][3], b0, b1);
                mma_tf32(c[1][n], a[1][0], a[1][1], a[1][2], a[1][3], b0, b1);
            }
        }
        __syncthreads();
    }

    // epilogue. col = n*8 + 2*tg + cc; rows g / g+8.  n<4: z gates, n+4: matching h gates.
    float bzv[4][2], bhv[4][2], wlv[4][2];
#pragma unroll
    for (int n = 0; n < 4; n++)
#pragma unroll
        for (int cc = 0; cc < 2; cc++) {
            int col = n * 8 + 2 * tg + cc;
            bzv[n][cc] = bz[col];
            bhv[n][cc] = bh[col];
            wlv[n][cc] = wl[col];
        }
    float bl0 = bl[0];

#pragma unroll
    for (int mf = 0; mf < 2; mf++) {
#pragma unroll
        for (int rh = 0; rh < 2; rh++) {
            float y = 0.f;
#pragma unroll
            for (int n = 0; n < 4; n++) {
#pragma unroll
                for (int cc = 0; cc < 2; cc++) {
                    float gz = c[mf][n    ][rh * 2 + cc] + bzv[n][cc];
                    float gh = c[mf][n + 4][rh * 2 + cc] + bhv[n][cc];
                    float z  = 1.f / (1.f + expf(-gz));
                    float ht = tanhf(gh);
                    float Hv = (1.f - z) * ht;
                    y += fmaxf(Hv, 0.f) * wlv[n][cc];
                }
            }
            y += __shfl_xor_sync(0xffffffffu, y, 1);
            y += __shfl_xor_sync(0xffffffffu, y, 2);
            if (tg == 0) {
                int node = blockm + w * 32 + mf * 16 + rh * 8 + g;
                if (node < N_NODES) out[node] = y + bl0;
            }
        }
    }
}

// ---------------- launch ----------------
// Fork/join topology (captured into the graph as parallel branches):
//   branch A (side stream): zero accumulators + build X16
//   main stream:            memset(deg) -> deg atomics -> pack+wprep
//   join, then:             prop1 -> prop2 -> gemm
// Streams/events are created per call and NOT destroyed (destroying a forked
// stream mid-capture would invalidate capture; kernel_launch runs only a few
// times, and stream objects are host-side, not device memory).
extern "C" void kernel_launch(void* const* d_in, const int* in_sizes, int n_in,
                              void* d_out, int out_size) {
    const float* x  = (const float*)d_in[0];
    const int*   ei = (const int*)d_in[1];
    const float* ew = (const float*)d_in[2];
    const float* Wz = (const float*)d_in[5];
    const float* bz = (const float*)d_in[6];
    const float* Wh = (const float*)d_in[9];
    const float* bh = (const float*)d_in[10];
    const float* Wl = (const float*)d_in[11];
    const float* bl = (const float*)d_in[12];
    float* out = (float*)d_out;

    const int* src = ei;
    const int* dst = ei + N_EDGES;

    void* p_deg;
    cudaGetSymbolAddress(&p_deg, g_deg);

    cudaStream_t sA;
    cudaStreamCreateWithFlags(&sA, cudaStreamNonBlocking);
    cudaEvent_t evFork, evJoin;
    cudaEventCreateWithFlags(&evFork, cudaEventDisableTiming);
    cudaEventCreateWithFlags(&evJoin, cudaEventDisableTiming);

    // fork: branch A inherits whatever precedes us in the captured stream
    cudaEventRecord(evFork, 0);
    cudaStreamWaitEvent(sA, evFork, 0);
    zero_x16_kernel<<<(NHF4 + 255) / 256, 256, 0, sA>>>(x);
    cudaEventRecord(evJoin, sA);

    // main chain
    cudaMemsetAsync(p_deg, 0, 2 * N_NODES * sizeof(float), 0);
    deg_kernel<<<(N_EDGES + 255) / 256, 256>>>(src, dst, ew);
    pack_wprep_kernel<<<(N_EDGES + 255) / 256, 256>>>(src, dst, ew, Wz, Wh);

    // join
    cudaStreamWaitEvent(0, evJoin, 0);

    prop1_kernel<<<(EHALF * 8 + 255) / 256, 256>>>();
    prop2_kernel<<<(EHALF * 8 + 255) / 256, 256>>>();
    gemm_kernel<<<(N_NODES + BM - 1) / BM, 128>>>(bz, bh, Wl, bl, out);
}